// round 12
// baseline (speedup 1.0000x reference)
#include <cuda_runtime.h>

#define DEV_INLINE __device__ __forceinline__
using u64 = unsigned long long;

constexpr int B_  = 8;
constexpr int TQ  = 256;
constexpr int TV  = 512;
constexpr int D_  = 256;
constexpr float SCALE2 = 2.8853900817779268f;   // 2*log2(e)
constexpr float LOG2E  = 1.4426950408889634f;

__device__ float g_qproj[B_ * TQ * D_];   // EQ  = 2^{SCALE2*(q@W1+b1)}
__device__ float g_vproj[B_ * TV * D_];   // EV' = 2^{SCALE2*(v@W2+b2) - 16}
__device__ float g_score[B_ * TQ * TV];   // scores, then alignment in-place

DEV_INLINE float fast_ex2(float x) { float y; asm("ex2.approx.f32 %0, %1;" : "=f"(y) : "f"(x)); return y; }

// ---- packed f32x2 helpers ----
DEV_INLINE u64 pk2(float lo, float hi) { u64 r; asm("mov.b64 %0, {%1, %2};" : "=l"(r) : "f"(lo), "f"(hi)); return r; }
DEV_INLINE void upk2(u64 p, float& lo, float& hi) { asm("mov.b64 {%0, %1}, %2;" : "=f"(lo), "=f"(hi) : "l"(p)); }
DEV_INLINE u64 bc2(float x) { u64 r; asm("mov.b64 %0, {%1, %1};" : "=l"(r) : "f"(x)); return r; }
DEV_INLINE u64 add2(u64 a, u64 b) { u64 r; asm("add.rn.f32x2 %0, %1, %2;" : "=l"(r) : "l"(a), "l"(b)); return r; }
DEV_INLINE u64 mul2(u64 a, u64 b) { u64 r; asm("mul.rn.f32x2 %0, %1, %2;" : "=l"(r) : "l"(a), "l"(b)); return r; }
DEV_INLINE u64 fma2(u64 a, u64 b, u64 c) { u64 r; asm("fma.rn.f32x2 %0, %1, %2, %3;" : "=l"(r) : "l"(a), "l"(b), "l"(c)); return r; }

DEV_INLINE u64 rcp2_pair(u64 a) {
    u64 r;
    asm("{\n\t.reg .f32 al, ah, rl, rh;\n\t"
        "mov.b64 {al, ah}, %1;\n\t"
        "rcp.approx.f32 rl, al;\n\t"
        "rcp.approx.f32 rh, ah;\n\t"
        "mov.b64 %0, {rl, rh};\n\t}"
        : "=l"(r) : "l"(a));
    return r;
}

// ---------------------------------------------------------------------------
// K1: BOTH projection GEMMs in one launch (blockIdx.y < 32 -> Q, else V),
// software-pipelined.
// ---------------------------------------------------------------------------
__global__ __launch_bounds__(256) void proj_kernel(
    const float* __restrict__ query, const float* __restrict__ value,
    const float* __restrict__ W1, const float* __restrict__ b1,
    const float* __restrict__ W2, const float* __restrict__ b2,
    float* __restrict__ qout, float* __restrict__ vout)
{
    __shared__ float sAT[16][64];
    __shared__ float sB[16][64];
    const int tid = threadIdx.x;
    const bool isQ = blockIdx.y < 32;
    const float* X    = isQ ? query : value;
    const float* W    = isQ ? W1 : W2;
    const float* bias = isQ ? b1 : b2;
    float* P          = isQ ? qout : vout;
    const float shift = isQ ? 0.0f : -16.0f;
    const int mb = (isQ ? blockIdx.y : (blockIdx.y - 32)) * 64;
    const int nb = blockIdx.x * 64;
    const int tm = tid >> 4, tn = tid & 15;
    const int arow = tid >> 2, akv = tid & 3;
    const int brow = tid >> 4, bcv = tid & 15;

    u64 acc2[2][4] = {};
    float4 av = *(const float4*)(X + (mb + arow) * D_ + akv * 4);
    float4 bv = *(const float4*)(W + brow * D_ + nb + bcv * 4);

    for (int kt = 0; kt < D_; kt += 16) {
        __syncthreads();
        sAT[akv*4+0][arow] = av.x; sAT[akv*4+1][arow] = av.y;
        sAT[akv*4+2][arow] = av.z; sAT[akv*4+3][arow] = av.w;
        *(float4*)&sB[brow][bcv*4] = bv;
        __syncthreads();
        if (kt + 16 < D_) {
            av = *(const float4*)(X + (mb + arow) * D_ + kt + 16 + akv * 4);
            bv = *(const float4*)(W + (kt + 16 + brow) * D_ + nb + bcv * 4);
        }
        #pragma unroll
        for (int k = 0; k < 16; k++) {
            float2 a01 = *(const float2*)&sAT[k][tm*4];
            float2 a23 = *(const float2*)&sAT[k][tm*4 + 2];
            float4 bq  = *(const float4*)&sB[k][tn*4];
            u64 A01 = pk2(a01.x, a01.y);
            u64 A23 = pk2(a23.x, a23.y);
            u64 B0 = bc2(bq.x), B1 = bc2(bq.y), B2 = bc2(bq.z), B3 = bc2(bq.w);
            acc2[0][0] = fma2(A01, B0, acc2[0][0]);
            acc2[0][1] = fma2(A01, B1, acc2[0][1]);
            acc2[0][2] = fma2(A01, B2, acc2[0][2]);
            acc2[0][3] = fma2(A01, B3, acc2[0][3]);
            acc2[1][0] = fma2(A23, B0, acc2[1][0]);
            acc2[1][1] = fma2(A23, B1, acc2[1][1]);
            acc2[1][2] = fma2(A23, B2, acc2[1][2]);
            acc2[1][3] = fma2(A23, B3, acc2[1][3]);
        }
    }
    float4 bias4 = *(const float4*)(bias + nb + tn*4);
    u64 S2 = pk2(SCALE2, SCALE2);
    u64 BS[4] = { bc2(bias4.x*SCALE2 + shift), bc2(bias4.y*SCALE2 + shift),
                  bc2(bias4.z*SCALE2 + shift), bc2(bias4.w*SCALE2 + shift) };
    #pragma unroll
    for (int ip = 0; ip < 2; ip++) {
        float lo[4], hi[4];
        #pragma unroll
        for (int j = 0; j < 4; j++) {
            u64 r = fma2(acc2[ip][j], S2, BS[j]);
            upk2(r, lo[j], hi[j]);
            lo[j] = fast_ex2(lo[j]);
            hi[j] = fast_ex2(hi[j]);
        }
        *(float4*)(P + (mb + tm*4 + ip*2 + 0) * D_ + nb + tn*4) = make_float4(lo[0], lo[1], lo[2], lo[3]);
        *(float4*)(P + (mb + tm*4 + ip*2 + 1) * D_ + nb + tn*4) = make_float4(hi[0], hi[1], hi[2], hi[3]);
    }
}

// ---------------------------------------------------------------------------
// K2: score = D - 2^-15 * sum 1/w;  w = fma(EQ, EV', 2^-16).
// d-paired lanes (natural layout), software-pipelined chunk loads.
// ---------------------------------------------------------------------------
__global__ __launch_bounds__(256) void score_kernel()
{
    __shared__ float sQ[64][36];
    __shared__ float sV[32][36];

    const int tid = threadIdx.x;
    const int b     = blockIdx.z;
    const int qbase = blockIdx.y * 64;
    const int jbase = blockIdx.x * 32;
    const float* qp = g_qproj + (size_t)(b * TQ + qbase) * D_;
    const float* vp = g_vproj + (size_t)(b * TV + jbase) * D_;
    const int tq = tid >> 4;
    const int tj = tid & 15;

    const int q0r = tid >> 3,         q0c = tid & 7;
    const int q1r = (256 + tid) >> 3, q1c = tid & 7;
    const int vr_ = tid >> 3,         vc_ = tid & 7;

    const u64 C16 = bc2(0x1p-16f);
    u64 acc[4][2] = {};

    float4 qreg0 = *(const float4*)(qp + q0r * D_ + q0c*4);
    float4 qreg1 = *(const float4*)(qp + q1r * D_ + q1c*4);
    float4 vreg  = *(const float4*)(vp + vr_ * D_ + vc_*4);

    for (int dc = 0; dc < D_; dc += 32) {
        __syncthreads();
        *(float4*)&sQ[q0r][q0c*4] = qreg0;
        *(float4*)&sQ[q1r][q1c*4] = qreg1;
        *(float4*)&sV[vr_][vc_*4] = vreg;
        __syncthreads();
        if (dc + 32 < D_) {
            qreg0 = *(const float4*)(qp + q0r * D_ + dc + 32 + q0c*4);
            qreg1 = *(const float4*)(qp + q1r * D_ + dc + 32 + q1c*4);
            vreg  = *(const float4*)(vp + vr_ * D_ + dc + 32 + vc_*4);
        }

        #pragma unroll
        for (int o = 0; o < 4; o++) {
            ulonglong2 v0[2], v1[2];
            #pragma unroll
            for (int j = 0; j < 2; j++) {
                v0[j] = *(const ulonglong2*)&sV[tj + 16*j][o*8];
                v1[j] = *(const ulonglong2*)&sV[tj + 16*j][o*8 + 4];
            }
            #pragma unroll
            for (int a = 0; a < 4; a++) {
                int r = 4*tq + a;
                ulonglong2 qa = *(const ulonglong2*)&sQ[r][o*8];
                ulonglong2 qb = *(const ulonglong2*)&sQ[r][o*8 + 4];
                #pragma unroll
                for (int j = 0; j < 2; j++) {
                    u64 w0 = fma2(qa.x, v0[j].x, C16);
                    u64 w1 = fma2(qa.y, v0[j].y, C16);
                    u64 w2 = fma2(qb.x, v1[j].x, C16);
                    u64 w3 = fma2(qb.y, v1[j].y, C16);
                    u64 p12 = mul2(w0, w1);
                    u64 p34 = mul2(w2, w3);
                    u64 num = fma2(p12, add2(w2, w3), mul2(p34, add2(w0, w1)));
                    u64 den = mul2(p12, p34);
                    acc[a][j] = fma2(num, rcp2_pair(den), acc[a][j]);
                }
            }
        }
    }

    #pragma unroll
    for (int a = 0; a < 4; a++)
        #pragma unroll
        for (int j = 0; j < 2; j++) {
            float lo, hi; upk2(acc[a][j], lo, hi);
            int qi = qbase + 4*tq + a;
            int jj = jbase + tj + 16*j;
            g_score[(size_t)(b * TQ + qi) * TV + jj] = (float)D_ - (lo + hi) * 0x1p-15f;
        }
}

// ---------------------------------------------------------------------------
// K3: softmax over TV=512 (16-row slab, warp per 2 rows) + transposed output.
// ---------------------------------------------------------------------------
__global__ __launch_bounds__(256) void softmax_kernel(float* __restrict__ out_at)
{
    __shared__ float sm[16][513];
    const int b    = blockIdx.x >> 4;
    const int slab = blockIdx.x & 15;
    const int q0   = slab * 16;
    const int wid  = threadIdx.x >> 5, lane = threadIdx.x & 31;

    #pragma unroll
    for (int rr = 0; rr < 2; rr++) {
        const int r = wid * 2 + rr;
        float* s = g_score + (size_t)(b * TQ + q0 + r) * TV;
        float4 v[4];
        #pragma unroll
        for (int k = 0; k < 4; k++) v[k] = *(const float4*)(s + (k*32 + lane)*4);
        float m = -1e30f;
        #pragma unroll
        for (int k = 0; k < 4; k++)
            m = fmaxf(m, fmaxf(fmaxf(v[k].x, v[k].y), fmaxf(v[k].z, v[k].w)));
        #pragma unroll
        for (int o = 16; o; o >>= 1) m = fmaxf(m, __shfl_xor_sync(0xffffffffu, m, o));

        float4 e[4]; float sum = 0.0f;
        #pragma unroll
        for (int k = 0; k < 4; k++) {
            e[k].x = fast_ex2((v[k].x - m) * LOG2E);
            e[k].y = fast_ex2((v[k].y - m) * LOG2E);
            e[k].z = fast_ex2((v[k].z - m) * LOG2E);
            e[k].w = fast_ex2((v[k].w - m) * LOG2E);
            sum += (e[k].x + e[k].y) + (e[k].z + e[k].w);
        }
        #pragma unroll
        for (int o = 16; o; o >>= 1) sum += __shfl_xor_sync(0xffffffffu, sum, o);
        float inv = 1.0f / sum;

        #pragma unroll
        for (int k = 0; k < 4; k++) {
            float4 a = make_float4(e[k].x*inv, e[k].y*inv, e[k].z*inv, e[k].w*inv);
            *(float4*)(s + (k*32 + lane)*4) = a;
            int col = (k*32 + lane)*4;
            sm[r][col+0] = a.x; sm[r][col+1] = a.y; sm[r][col+2] = a.z; sm[r][col+3] = a.w;
        }
    }
    __syncthreads();

    const int i = lane & 15;
    const int jb = wid * 64 + (lane >> 4) * 32;
    float* dst = out_at + (size_t)(b * TV) * TQ + q0 + i;
    #pragma unroll
    for (int jj = 0; jj < 32; jj++) {
        int j = jb + jj;
        dst[(size_t)j * TQ] = sm[i][j];
    }
}

// ---------------------------------------------------------------------------
// K4: context[b] = alignment[b] @ value[b] + fused query concat.
// 512 threads (16 warps/SM): thread = 1 q-pair x 4 n; loaders split A/B.
// ---------------------------------------------------------------------------
__global__ __launch_bounds__(512) void context_kernel(
    const float* __restrict__ value, const float* __restrict__ query,
    float* __restrict__ out)
{
    __shared__ float sAT[16][64];
    __shared__ float sB[16][64];
    const int tid = threadIdx.x;
    const int b  = blockIdx.z;
    const int mb = blockIdx.y * 64;
    const int nb = blockIdx.x * 64;
    const float* A = g_score + (size_t)b * TQ * TV;
    const float* V = value + (size_t)b * TV * D_;
    float* C = out + (size_t)b * TQ * (2 * D_);
    const int tpq = tid >> 4;      // 0..31 q-pair
    const int tn  = tid & 15;      // 0..15 n-quad

    const bool loadA = tid < 256;
    const int arow = tid >> 2, akv = tid & 3;                 // tid < 256
    const int brow = (tid - 256) >> 4, bcv = (tid - 256) & 15;// tid >= 256

    u64 acc[4] = {};
    float4 ld;
    if (loadA) ld = *(const float4*)(A + (mb + arow) * TV + akv * 4);
    else       ld = *(const float4*)(V + brow * D_ + nb + bcv * 4);

    for (int kt = 0; kt < TV; kt += 16) {
        __syncthreads();
        if (loadA) {
            sAT[akv*4+0][arow] = ld.x; sAT[akv*4+1][arow] = ld.y;
            sAT[akv*4+2][arow] = ld.z; sAT[akv*4+3][arow] = ld.w;
        } else {
            *(float4*)&sB[brow][bcv*4] = ld;
        }
        __syncthreads();
        if (kt + 16 < TV) {
            if (loadA) ld = *(const float4*)(A + (mb + arow) * TV + kt + 16 + akv * 4);
            else       ld = *(const float4*)(V + (kt + 16 + brow) * D_ + nb + bcv * 4);
        }
        #pragma unroll
        for (int k = 0; k < 16; k++) {
            float2 a01 = *(const float2*)&sAT[k][tpq*2];
            float4 bq  = *(const float4*)&sB[k][tn*4];
            u64 A01 = pk2(a01.x, a01.y);
            acc[0] = fma2(A01, bc2(bq.x), acc[0]);
            acc[1] = fma2(A01, bc2(bq.y), acc[1]);
            acc[2] = fma2(A01, bc2(bq.z), acc[2]);
            acc[3] = fma2(A01, bc2(bq.w), acc[3]);
        }
    }
    {
        float lo[4], hi[4];
        #pragma unroll
        for (int j = 0; j < 4; j++) upk2(acc[j], lo[j], hi[j]);
        *(float4*)(C + (mb + tpq*2 + 0) * (2 * D_) + nb + tn*4) = make_float4(lo[0], lo[1], lo[2], lo[3]);
        *(float4*)(C + (mb + tpq*2 + 1) * (2 * D_) + nb + tn*4) = make_float4(hi[0], hi[1], hi[2], hi[3]);
    }

    // fused query concat: out[b][mb..][D + nb..] = query[b][mb..][nb..]
    const float* Q = query + (size_t)b * TQ * D_;
    #pragma unroll
    for (int i = 0; i < 2; i++) {
        int idx = i * 512 + tid;               // 1024 float4s in 64x64 block
        int r = idx >> 4, c = idx & 15;
        *(float4*)(C + (mb + r) * (2 * D_) + D_ + nb + c*4) =
            *(const float4*)(Q + (mb + r) * D_ + nb + c*4);
    }
}

// ---------------------------------------------------------------------------
extern "C" void kernel_launch(void* const* d_in, const int* in_sizes, int n_in,
                              void* d_out, int out_size)
{
    const float* query = (const float*)d_in[0];   // [8,256,256]
    const float* value = (const float*)d_in[1];   // [8,512,256]
    const float* W1    = (const float*)d_in[2];   // [256,256]
    const float* b1    = (const float*)d_in[3];   // [256]
    const float* W2    = (const float*)d_in[4];   // [256,256]
    const float* b2    = (const float*)d_in[5];   // [256]
    float* out = (float*)d_out;

    void *qp_, *vp_;
    cudaGetSymbolAddress(&qp_, g_qproj);
    cudaGetSymbolAddress(&vp_, g_vproj);

    proj_kernel<<<dim3(4, 96), 256>>>(query, value, W1, b1, W2, b2,
                                      (float*)qp_, (float*)vp_);
    score_kernel<<<dim3(16, 4, 8), 256>>>();
    softmax_kernel<<<128, 256>>>(out + B_ * TQ * 2 * D_);
    context_kernel<<<dim3(4, 4, 8), 512>>>(value, query, out);
}

// round 13
// speedup vs baseline: 1.0197x; 1.0197x over previous
#include <cuda_runtime.h>

#define DEV_INLINE __device__ __forceinline__
using u64 = unsigned long long;

constexpr int B_  = 8;
constexpr int TQ  = 256;
constexpr int TV  = 512;
constexpr int D_  = 256;
constexpr float SCALE2 = 2.8853900817779268f;   // 2*log2(e)
constexpr float LOG2E  = 1.4426950408889634f;

__device__ float g_qproj[B_ * TQ * D_];   // EQ  = 2^{SCALE2*(q@W1+b1)}
__device__ float g_vproj[B_ * TV * D_];   // EV' = 2^{SCALE2*(v@W2+b2) - 16}
__device__ float g_score[B_ * TQ * TV];   // scores, then alignment in-place

DEV_INLINE float fast_ex2(float x) { float y; asm("ex2.approx.f32 %0, %1;" : "=f"(y) : "f"(x)); return y; }

// ---- packed f32x2 helpers ----
DEV_INLINE u64 pk2(float lo, float hi) { u64 r; asm("mov.b64 %0, {%1, %2};" : "=l"(r) : "f"(lo), "f"(hi)); return r; }
DEV_INLINE void upk2(u64 p, float& lo, float& hi) { asm("mov.b64 {%0, %1}, %2;" : "=f"(lo), "=f"(hi) : "l"(p)); }
DEV_INLINE u64 bc2(float x) { u64 r; asm("mov.b64 %0, {%1, %1};" : "=l"(r) : "f"(x)); return r; }
DEV_INLINE u64 add2(u64 a, u64 b) { u64 r; asm("add.rn.f32x2 %0, %1, %2;" : "=l"(r) : "l"(a), "l"(b)); return r; }
DEV_INLINE u64 mul2(u64 a, u64 b) { u64 r; asm("mul.rn.f32x2 %0, %1, %2;" : "=l"(r) : "l"(a), "l"(b)); return r; }
DEV_INLINE u64 fma2(u64 a, u64 b, u64 c) { u64 r; asm("fma.rn.f32x2 %0, %1, %2, %3;" : "=l"(r) : "l"(a), "l"(b), "l"(c)); return r; }

DEV_INLINE u64 rcp2_pair(u64 a) {
    u64 r;
    asm("{\n\t.reg .f32 al, ah, rl, rh;\n\t"
        "mov.b64 {al, ah}, %1;\n\t"
        "rcp.approx.f32 rl, al;\n\t"
        "rcp.approx.f32 rh, ah;\n\t"
        "mov.b64 %0, {rl, rh};\n\t}"
        : "=l"(r) : "l"(a));
    return r;
}

// ---------------------------------------------------------------------------
// K1: BOTH projection GEMMs in one launch (blockIdx.y < 32 -> Q, else V),
// software-pipelined.
// ---------------------------------------------------------------------------
__global__ __launch_bounds__(256) void proj_kernel(
    const float* __restrict__ query, const float* __restrict__ value,
    const float* __restrict__ W1, const float* __restrict__ b1,
    const float* __restrict__ W2, const float* __restrict__ b2,
    float* __restrict__ qout, float* __restrict__ vout)
{
    __shared__ float sAT[16][64];
    __shared__ float sB[16][64];
    const int tid = threadIdx.x;
    const bool isQ = blockIdx.y < 32;
    const float* X    = isQ ? query : value;
    const float* W    = isQ ? W1 : W2;
    const float* bias = isQ ? b1 : b2;
    float* P          = isQ ? qout : vout;
    const float shift = isQ ? 0.0f : -16.0f;
    const int mb = (isQ ? blockIdx.y : (blockIdx.y - 32)) * 64;
    const int nb = blockIdx.x * 64;
    const int tm = tid >> 4, tn = tid & 15;
    const int arow = tid >> 2, akv = tid & 3;
    const int brow = tid >> 4, bcv = tid & 15;

    u64 acc2[2][4] = {};
    float4 av = *(const float4*)(X + (mb + arow) * D_ + akv * 4);
    float4 bv = *(const float4*)(W + brow * D_ + nb + bcv * 4);

    for (int kt = 0; kt < D_; kt += 16) {
        __syncthreads();
        sAT[akv*4+0][arow] = av.x; sAT[akv*4+1][arow] = av.y;
        sAT[akv*4+2][arow] = av.z; sAT[akv*4+3][arow] = av.w;
        *(float4*)&sB[brow][bcv*4] = bv;
        __syncthreads();
        if (kt + 16 < D_) {
            av = *(const float4*)(X + (mb + arow) * D_ + kt + 16 + akv * 4);
            bv = *(const float4*)(W + (kt + 16 + brow) * D_ + nb + bcv * 4);
        }
        #pragma unroll
        for (int k = 0; k < 16; k++) {
            float2 a01 = *(const float2*)&sAT[k][tm*4];
            float2 a23 = *(const float2*)&sAT[k][tm*4 + 2];
            float4 bq  = *(const float4*)&sB[k][tn*4];
            u64 A01 = pk2(a01.x, a01.y);
            u64 A23 = pk2(a23.x, a23.y);
            u64 B0 = bc2(bq.x), B1 = bc2(bq.y), B2 = bc2(bq.z), B3 = bc2(bq.w);
            acc2[0][0] = fma2(A01, B0, acc2[0][0]);
            acc2[0][1] = fma2(A01, B1, acc2[0][1]);
            acc2[0][2] = fma2(A01, B2, acc2[0][2]);
            acc2[0][3] = fma2(A01, B3, acc2[0][3]);
            acc2[1][0] = fma2(A23, B0, acc2[1][0]);
            acc2[1][1] = fma2(A23, B1, acc2[1][1]);
            acc2[1][2] = fma2(A23, B2, acc2[1][2]);
            acc2[1][3] = fma2(A23, B3, acc2[1][3]);
        }
    }
    float4 bias4 = *(const float4*)(bias + nb + tn*4);
    u64 S2 = pk2(SCALE2, SCALE2);
    u64 BS[4] = { bc2(bias4.x*SCALE2 + shift), bc2(bias4.y*SCALE2 + shift),
                  bc2(bias4.z*SCALE2 + shift), bc2(bias4.w*SCALE2 + shift) };
    #pragma unroll
    for (int ip = 0; ip < 2; ip++) {
        float lo[4], hi[4];
        #pragma unroll
        for (int j = 0; j < 4; j++) {
            u64 r = fma2(acc2[ip][j], S2, BS[j]);
            upk2(r, lo[j], hi[j]);
            lo[j] = fast_ex2(lo[j]);
            hi[j] = fast_ex2(hi[j]);
        }
        *(float4*)(P + (mb + tm*4 + ip*2 + 0) * D_ + nb + tn*4) = make_float4(lo[0], lo[1], lo[2], lo[3]);
        *(float4*)(P + (mb + tm*4 + ip*2 + 1) * D_ + nb + tn*4) = make_float4(hi[0], hi[1], hi[2], hi[3]);
    }
}

// ---------------------------------------------------------------------------
// K2: score = D - 2^-15 * sum 1/w;  w = fma(EQ, EV', 2^-16).
// d-paired lanes (natural layout), software-pipelined chunk loads.
// ---------------------------------------------------------------------------
__global__ __launch_bounds__(256) void score_kernel()
{
    __shared__ float sQ[64][36];
    __shared__ float sV[32][36];

    const int tid = threadIdx.x;
    const int b     = blockIdx.z;
    const int qbase = blockIdx.y * 64;
    const int jbase = blockIdx.x * 32;
    const float* qp = g_qproj + (size_t)(b * TQ + qbase) * D_;
    const float* vp = g_vproj + (size_t)(b * TV + jbase) * D_;
    const int tq = tid >> 4;
    const int tj = tid & 15;

    const int q0r = tid >> 3,         q0c = tid & 7;
    const int q1r = (256 + tid) >> 3, q1c = tid & 7;
    const int vr_ = tid >> 3,         vc_ = tid & 7;

    const u64 C16 = bc2(0x1p-16f);
    u64 acc[4][2] = {};

    float4 qreg0 = *(const float4*)(qp + q0r * D_ + q0c*4);
    float4 qreg1 = *(const float4*)(qp + q1r * D_ + q1c*4);
    float4 vreg  = *(const float4*)(vp + vr_ * D_ + vc_*4);

    for (int dc = 0; dc < D_; dc += 32) {
        __syncthreads();
        *(float4*)&sQ[q0r][q0c*4] = qreg0;
        *(float4*)&sQ[q1r][q1c*4] = qreg1;
        *(float4*)&sV[vr_][vc_*4] = vreg;
        __syncthreads();
        if (dc + 32 < D_) {
            qreg0 = *(const float4*)(qp + q0r * D_ + dc + 32 + q0c*4);
            qreg1 = *(const float4*)(qp + q1r * D_ + dc + 32 + q1c*4);
            vreg  = *(const float4*)(vp + vr_ * D_ + dc + 32 + vc_*4);
        }

        #pragma unroll
        for (int o = 0; o < 4; o++) {
            ulonglong2 v0[2], v1[2];
            #pragma unroll
            for (int j = 0; j < 2; j++) {
                v0[j] = *(const ulonglong2*)&sV[tj + 16*j][o*8];
                v1[j] = *(const ulonglong2*)&sV[tj + 16*j][o*8 + 4];
            }
            #pragma unroll
            for (int a = 0; a < 4; a++) {
                int r = 4*tq + a;
                ulonglong2 qa = *(const ulonglong2*)&sQ[r][o*8];
                ulonglong2 qb = *(const ulonglong2*)&sQ[r][o*8 + 4];
                #pragma unroll
                for (int j = 0; j < 2; j++) {
                    u64 w0 = fma2(qa.x, v0[j].x, C16);
                    u64 w1 = fma2(qa.y, v0[j].y, C16);
                    u64 w2 = fma2(qb.x, v1[j].x, C16);
                    u64 w3 = fma2(qb.y, v1[j].y, C16);
                    u64 p12 = mul2(w0, w1);
                    u64 p34 = mul2(w2, w3);
                    u64 num = fma2(p12, add2(w2, w3), mul2(p34, add2(w0, w1)));
                    u64 den = mul2(p12, p34);
                    acc[a][j] = fma2(num, rcp2_pair(den), acc[a][j]);
                }
            }
        }
    }

    #pragma unroll
    for (int a = 0; a < 4; a++)
        #pragma unroll
        for (int j = 0; j < 2; j++) {
            float lo, hi; upk2(acc[a][j], lo, hi);
            int qi = qbase + 4*tq + a;
            int jj = jbase + tj + 16*j;
            g_score[(size_t)(b * TQ + qi) * TV + jj] = (float)D_ - (lo + hi) * 0x1p-15f;
        }
}

// ---------------------------------------------------------------------------
// K3: softmax over TV=512 (16-row slab, warp per 2 rows) + transposed output.
// ---------------------------------------------------------------------------
__global__ __launch_bounds__(256) void softmax_kernel(float* __restrict__ out_at)
{
    __shared__ float sm[16][513];
    const int b    = blockIdx.x >> 4;
    const int slab = blockIdx.x & 15;
    const int q0   = slab * 16;
    const int wid  = threadIdx.x >> 5, lane = threadIdx.x & 31;

    #pragma unroll
    for (int rr = 0; rr < 2; rr++) {
        const int r = wid * 2 + rr;
        float* s = g_score + (size_t)(b * TQ + q0 + r) * TV;
        float4 v[4];
        #pragma unroll
        for (int k = 0; k < 4; k++) v[k] = *(const float4*)(s + (k*32 + lane)*4);
        float m = -1e30f;
        #pragma unroll
        for (int k = 0; k < 4; k++)
            m = fmaxf(m, fmaxf(fmaxf(v[k].x, v[k].y), fmaxf(v[k].z, v[k].w)));
        #pragma unroll
        for (int o = 16; o; o >>= 1) m = fmaxf(m, __shfl_xor_sync(0xffffffffu, m, o));

        float4 e[4]; float sum = 0.0f;
        #pragma unroll
        for (int k = 0; k < 4; k++) {
            e[k].x = fast_ex2((v[k].x - m) * LOG2E);
            e[k].y = fast_ex2((v[k].y - m) * LOG2E);
            e[k].z = fast_ex2((v[k].z - m) * LOG2E);
            e[k].w = fast_ex2((v[k].w - m) * LOG2E);
            sum += (e[k].x + e[k].y) + (e[k].z + e[k].w);
        }
        #pragma unroll
        for (int o = 16; o; o >>= 1) sum += __shfl_xor_sync(0xffffffffu, sum, o);
        float inv = 1.0f / sum;

        #pragma unroll
        for (int k = 0; k < 4; k++) {
            float4 a = make_float4(e[k].x*inv, e[k].y*inv, e[k].z*inv, e[k].w*inv);
            *(float4*)(s + (k*32 + lane)*4) = a;
            int col = (k*32 + lane)*4;
            sm[r][col+0] = a.x; sm[r][col+1] = a.y; sm[r][col+2] = a.z; sm[r][col+3] = a.w;
        }
    }
    __syncthreads();

    const int i = lane & 15;
    const int jb = wid * 64 + (lane >> 4) * 32;
    float* dst = out_at + (size_t)(b * TV) * TQ + q0 + i;
    #pragma unroll
    for (int jj = 0; jj < 32; jj++) {
        int j = jb + jj;
        dst[(size_t)j * TQ] = sm[i][j];
    }
}

// ---------------------------------------------------------------------------
// K4: context[b] = alignment[b] @ value[b] + fused query concat.
// 32x32 tile, 128 threads, 512 blocks (~3.5 blocks/SM -> ~14 warps/SM).
// acc lanes = (n, n+1) pairs: B loads as NATIVE u64 pairs, A broadcast (2 bc2).
// ---------------------------------------------------------------------------
__global__ __launch_bounds__(128) void context_kernel(
    const float* __restrict__ value, const float* __restrict__ query,
    float* __restrict__ out)
{
    __shared__ float sAT[16][34];   // pitch 34: LDS.64 aligned, store-spread
    __shared__ float sB[16][36];    // pitch 36: LDS.128 16B-aligned
    const int tid = threadIdx.x;
    const int b  = blockIdx.z;
    const int mb = blockIdx.y * 32;
    const int nb = blockIdx.x * 32;
    const float* A = g_score + (size_t)b * TQ * TV;
    const float* V = value + (size_t)b * TV * D_;
    float* C = out + (size_t)b * TQ * (2 * D_);
    const int tq = tid >> 3;       // 0..15 -> q rows 2tq, 2tq+1
    const int tn = tid & 7;        // 0..7  -> n cols 4tn..4tn+3
    const int arow = tid >> 2, akv = tid & 3;   // A loader: 32 rows x 4 f4
    const int brow = tid >> 3, bcv = tid & 7;   // B loader: 16 rows x 8 f4

    u64 acc[2][2] = {};            // [qrow][npair]
    float4 av = *(const float4*)(A + (mb + arow) * TV + akv * 4);
    float4 bv = *(const float4*)(V + brow * D_ + nb + bcv * 4);

    for (int kt = 0; kt < TV; kt += 16) {
        __syncthreads();
        sAT[akv*4+0][arow] = av.x; sAT[akv*4+1][arow] = av.y;
        sAT[akv*4+2][arow] = av.z; sAT[akv*4+3][arow] = av.w;
        *(float4*)&sB[brow][bcv*4] = bv;
        __syncthreads();
        if (kt + 16 < TV) {
            av = *(const float4*)(A + (mb + arow) * TV + kt + 16 + akv * 4);
            bv = *(const float4*)(V + (kt + 16 + brow) * D_ + nb + bcv * 4);
        }
        #pragma unroll
        for (int k = 0; k < 16; k++) {
            float2 a01 = *(const float2*)&sAT[k][tq*2];
            ulonglong2 bq = *(const ulonglong2*)&sB[k][tn*4];
            u64 A0 = bc2(a01.x), A1 = bc2(a01.y);
            acc[0][0] = fma2(A0, bq.x, acc[0][0]);
            acc[0][1] = fma2(A0, bq.y, acc[0][1]);
            acc[1][0] = fma2(A1, bq.x, acc[1][0]);
            acc[1][1] = fma2(A1, bq.y, acc[1][1]);
        }
    }
    #pragma unroll
    for (int i = 0; i < 2; i++) {
        float lo0, hi0, lo1, hi1;
        upk2(acc[i][0], lo0, hi0);
        upk2(acc[i][1], lo1, hi1);
        *(float4*)(C + (mb + tq*2 + i) * (2 * D_) + nb + tn*4) =
            make_float4(lo0, hi0, lo1, hi1);
    }

    // fused query concat: out[b][mb..][D + nb..] = query[b][mb..][nb..]
    const float* Q = query + (size_t)b * TQ * D_;
    #pragma unroll
    for (int i = 0; i < 2; i++) {
        int idx = i * 128 + tid;               // 256 float4s in 32x32 block
        int r = idx >> 3, c = idx & 7;
        *(float4*)(C + (mb + r) * (2 * D_) + D_ + nb + c*4) =
            *(const float4*)(Q + (mb + r) * D_ + nb + c*4);
    }
}

// ---------------------------------------------------------------------------
extern "C" void kernel_launch(void* const* d_in, const int* in_sizes, int n_in,
                              void* d_out, int out_size)
{
    const float* query = (const float*)d_in[0];   // [8,256,256]
    const float* value = (const float*)d_in[1];   // [8,512,256]
    const float* W1    = (const float*)d_in[2];   // [256,256]
    const float* b1    = (const float*)d_in[3];   // [256]
    const float* W2    = (const float*)d_in[4];   // [256,256]
    const float* b2    = (const float*)d_in[5];   // [256]
    float* out = (float*)d_out;

    void *qp_, *vp_;
    cudaGetSymbolAddress(&qp_, g_qproj);
    cudaGetSymbolAddress(&vp_, g_vproj);

    proj_kernel<<<dim3(4, 96), 256>>>(query, value, W1, b1, W2, b2,
                                      (float*)qp_, (float*)vp_);
    score_kernel<<<dim3(16, 4, 8), 256>>>();
    softmax_kernel<<<128, 256>>>(out + B_ * TQ * 2 * D_);
    context_kernel<<<dim3(8, 8, 8), 128>>>(value, query, out);
}

// round 14
// speedup vs baseline: 1.1005x; 1.0793x over previous
#include <cuda_runtime.h>

#define DEV_INLINE __device__ __forceinline__
using u64 = unsigned long long;

constexpr int B_  = 8;
constexpr int TQ  = 256;
constexpr int TV  = 512;
constexpr int D_  = 256;
constexpr float SCALE2 = 2.8853900817779268f;   // 2*log2(e)
constexpr float LOG2E  = 1.4426950408889634f;

__device__ float g_qproj[B_ * TQ * D_];   // EQ  = 2^{SCALE2*(q@W1+b1)}
__device__ float g_vproj[B_ * TV * D_];   // EV' = 2^{SCALE2*(v@W2+b2) - 16}
__device__ float g_score[B_ * TQ * TV];   // scores, then alignment in-place

DEV_INLINE float fast_ex2(float x) { float y; asm("ex2.approx.f32 %0, %1;" : "=f"(y) : "f"(x)); return y; }

// ---- packed f32x2 helpers ----
DEV_INLINE u64 pk2(float lo, float hi) { u64 r; asm("mov.b64 %0, {%1, %2};" : "=l"(r) : "f"(lo), "f"(hi)); return r; }
DEV_INLINE void upk2(u64 p, float& lo, float& hi) { asm("mov.b64 {%0, %1}, %2;" : "=f"(lo), "=f"(hi) : "l"(p)); }
DEV_INLINE u64 bc2(float x) { u64 r; asm("mov.b64 %0, {%1, %1};" : "=l"(r) : "f"(x)); return r; }
DEV_INLINE u64 add2(u64 a, u64 b) { u64 r; asm("add.rn.f32x2 %0, %1, %2;" : "=l"(r) : "l"(a), "l"(b)); return r; }
DEV_INLINE u64 mul2(u64 a, u64 b) { u64 r; asm("mul.rn.f32x2 %0, %1, %2;" : "=l"(r) : "l"(a), "l"(b)); return r; }
DEV_INLINE u64 fma2(u64 a, u64 b, u64 c) { u64 r; asm("fma.rn.f32x2 %0, %1, %2, %3;" : "=l"(r) : "l"(a), "l"(b), "l"(c)); return r; }

DEV_INLINE u64 rcp2_pair(u64 a) {
    u64 r;
    asm("{\n\t.reg .f32 al, ah, rl, rh;\n\t"
        "mov.b64 {al, ah}, %1;\n\t"
        "rcp.approx.f32 rl, al;\n\t"
        "rcp.approx.f32 rh, ah;\n\t"
        "mov.b64 %0, {rl, rh};\n\t}"
        : "=l"(r) : "l"(a));
    return r;
}

// ---------------------------------------------------------------------------
// K1: BOTH projection GEMMs in one launch (blockIdx.y < 32 -> Q, else V),
// software-pipelined.
// ---------------------------------------------------------------------------
__global__ __launch_bounds__(256) void proj_kernel(
    const float* __restrict__ query, const float* __restrict__ value,
    const float* __restrict__ W1, const float* __restrict__ b1,
    const float* __restrict__ W2, const float* __restrict__ b2,
    float* __restrict__ qout, float* __restrict__ vout)
{
    __shared__ float sAT[16][64];
    __shared__ float sB[16][64];
    const int tid = threadIdx.x;
    const bool isQ = blockIdx.y < 32;
    const float* X    = isQ ? query : value;
    const float* W    = isQ ? W1 : W2;
    const float* bias = isQ ? b1 : b2;
    float* P          = isQ ? qout : vout;
    const float shift = isQ ? 0.0f : -16.0f;
    const int mb = (isQ ? blockIdx.y : (blockIdx.y - 32)) * 64;
    const int nb = blockIdx.x * 64;
    const int tm = tid >> 4, tn = tid & 15;
    const int arow = tid >> 2, akv = tid & 3;
    const int brow = tid >> 4, bcv = tid & 15;

    u64 acc2[2][4] = {};
    float4 av = *(const float4*)(X + (mb + arow) * D_ + akv * 4);
    float4 bv = *(const float4*)(W + brow * D_ + nb + bcv * 4);

    for (int kt = 0; kt < D_; kt += 16) {
        __syncthreads();
        sAT[akv*4+0][arow] = av.x; sAT[akv*4+1][arow] = av.y;
        sAT[akv*4+2][arow] = av.z; sAT[akv*4+3][arow] = av.w;
        *(float4*)&sB[brow][bcv*4] = bv;
        __syncthreads();
        if (kt + 16 < D_) {
            av = *(const float4*)(X + (mb + arow) * D_ + kt + 16 + akv * 4);
            bv = *(const float4*)(W + (kt + 16 + brow) * D_ + nb + bcv * 4);
        }
        #pragma unroll
        for (int k = 0; k < 16; k++) {
            float2 a01 = *(const float2*)&sAT[k][tm*4];
            float2 a23 = *(const float2*)&sAT[k][tm*4 + 2];
            float4 bq  = *(const float4*)&sB[k][tn*4];
            u64 A01 = pk2(a01.x, a01.y);
            u64 A23 = pk2(a23.x, a23.y);
            u64 B0 = bc2(bq.x), B1 = bc2(bq.y), B2 = bc2(bq.z), B3 = bc2(bq.w);
            acc2[0][0] = fma2(A01, B0, acc2[0][0]);
            acc2[0][1] = fma2(A01, B1, acc2[0][1]);
            acc2[0][2] = fma2(A01, B2, acc2[0][2]);
            acc2[0][3] = fma2(A01, B3, acc2[0][3]);
            acc2[1][0] = fma2(A23, B0, acc2[1][0]);
            acc2[1][1] = fma2(A23, B1, acc2[1][1]);
            acc2[1][2] = fma2(A23, B2, acc2[1][2]);
            acc2[1][3] = fma2(A23, B3, acc2[1][3]);
        }
    }
    float4 bias4 = *(const float4*)(bias + nb + tn*4);
    u64 S2 = pk2(SCALE2, SCALE2);
    u64 BS[4] = { bc2(bias4.x*SCALE2 + shift), bc2(bias4.y*SCALE2 + shift),
                  bc2(bias4.z*SCALE2 + shift), bc2(bias4.w*SCALE2 + shift) };
    #pragma unroll
    for (int ip = 0; ip < 2; ip++) {
        float lo[4], hi[4];
        #pragma unroll
        for (int j = 0; j < 4; j++) {
            u64 r = fma2(acc2[ip][j], S2, BS[j]);
            upk2(r, lo[j], hi[j]);
            lo[j] = fast_ex2(lo[j]);
            hi[j] = fast_ex2(hi[j]);
        }
        *(float4*)(P + (mb + tm*4 + ip*2 + 0) * D_ + nb + tn*4) = make_float4(lo[0], lo[1], lo[2], lo[3]);
        *(float4*)(P + (mb + tm*4 + ip*2 + 1) * D_ + nb + tn*4) = make_float4(hi[0], hi[1], hi[2], hi[3]);
    }
}

// ---------------------------------------------------------------------------
// K2: score = D - 2^-15 * sum 1/w;  w = fma(EQ, EV', 2^-16).
// d-paired lanes (natural layout), software-pipelined chunk loads.
// ---------------------------------------------------------------------------
__global__ __launch_bounds__(256) void score_kernel()
{
    __shared__ float sQ[64][36];
    __shared__ float sV[32][36];

    const int tid = threadIdx.x;
    const int b     = blockIdx.z;
    const int qbase = blockIdx.y * 64;
    const int jbase = blockIdx.x * 32;
    const float* qp = g_qproj + (size_t)(b * TQ + qbase) * D_;
    const float* vp = g_vproj + (size_t)(b * TV + jbase) * D_;
    const int tq = tid >> 4;
    const int tj = tid & 15;

    const int q0r = tid >> 3,         q0c = tid & 7;
    const int q1r = (256 + tid) >> 3, q1c = tid & 7;
    const int vr_ = tid >> 3,         vc_ = tid & 7;

    const u64 C16 = bc2(0x1p-16f);
    u64 acc[4][2] = {};

    float4 qreg0 = *(const float4*)(qp + q0r * D_ + q0c*4);
    float4 qreg1 = *(const float4*)(qp + q1r * D_ + q1c*4);
    float4 vreg  = *(const float4*)(vp + vr_ * D_ + vc_*4);

    for (int dc = 0; dc < D_; dc += 32) {
        __syncthreads();
        *(float4*)&sQ[q0r][q0c*4] = qreg0;
        *(float4*)&sQ[q1r][q1c*4] = qreg1;
        *(float4*)&sV[vr_][vc_*4] = vreg;
        __syncthreads();
        if (dc + 32 < D_) {
            qreg0 = *(const float4*)(qp + q0r * D_ + dc + 32 + q0c*4);
            qreg1 = *(const float4*)(qp + q1r * D_ + dc + 32 + q1c*4);
            vreg  = *(const float4*)(vp + vr_ * D_ + dc + 32 + vc_*4);
        }

        #pragma unroll
        for (int o = 0; o < 4; o++) {
            ulonglong2 v0[2], v1[2];
            #pragma unroll
            for (int j = 0; j < 2; j++) {
                v0[j] = *(const ulonglong2*)&sV[tj + 16*j][o*8];
                v1[j] = *(const ulonglong2*)&sV[tj + 16*j][o*8 + 4];
            }
            #pragma unroll
            for (int a = 0; a < 4; a++) {
                int r = 4*tq + a;
                ulonglong2 qa = *(const ulonglong2*)&sQ[r][o*8];
                ulonglong2 qb = *(const ulonglong2*)&sQ[r][o*8 + 4];
                #pragma unroll
                for (int j = 0; j < 2; j++) {
                    u64 w0 = fma2(qa.x, v0[j].x, C16);
                    u64 w1 = fma2(qa.y, v0[j].y, C16);
                    u64 w2 = fma2(qb.x, v1[j].x, C16);
                    u64 w3 = fma2(qb.y, v1[j].y, C16);
                    u64 p12 = mul2(w0, w1);
                    u64 p34 = mul2(w2, w3);
                    u64 num = fma2(p12, add2(w2, w3), mul2(p34, add2(w0, w1)));
                    u64 den = mul2(p12, p34);
                    acc[a][j] = fma2(num, rcp2_pair(den), acc[a][j]);
                }
            }
        }
    }

    #pragma unroll
    for (int a = 0; a < 4; a++)
        #pragma unroll
        for (int j = 0; j < 2; j++) {
            float lo, hi; upk2(acc[a][j], lo, hi);
            int qi = qbase + 4*tq + a;
            int jj = jbase + tj + 16*j;
            g_score[(size_t)(b * TQ + qi) * TV + jj] = (float)D_ - (lo + hi) * 0x1p-15f;
        }
}

// ---------------------------------------------------------------------------
// K3: softmax over TV=512 (16-row slab, warp per 2 rows) + transposed output.
// ---------------------------------------------------------------------------
__global__ __launch_bounds__(256) void softmax_kernel(float* __restrict__ out_at)
{
    __shared__ float sm[16][513];
    const int b    = blockIdx.x >> 4;
    const int slab = blockIdx.x & 15;
    const int q0   = slab * 16;
    const int wid  = threadIdx.x >> 5, lane = threadIdx.x & 31;

    #pragma unroll
    for (int rr = 0; rr < 2; rr++) {
        const int r = wid * 2 + rr;
        float* s = g_score + (size_t)(b * TQ + q0 + r) * TV;
        float4 v[4];
        #pragma unroll
        for (int k = 0; k < 4; k++) v[k] = *(const float4*)(s + (k*32 + lane)*4);
        float m = -1e30f;
        #pragma unroll
        for (int k = 0; k < 4; k++)
            m = fmaxf(m, fmaxf(fmaxf(v[k].x, v[k].y), fmaxf(v[k].z, v[k].w)));
        #pragma unroll
        for (int o = 16; o; o >>= 1) m = fmaxf(m, __shfl_xor_sync(0xffffffffu, m, o));

        float4 e[4]; float sum = 0.0f;
        #pragma unroll
        for (int k = 0; k < 4; k++) {
            e[k].x = fast_ex2((v[k].x - m) * LOG2E);
            e[k].y = fast_ex2((v[k].y - m) * LOG2E);
            e[k].z = fast_ex2((v[k].z - m) * LOG2E);
            e[k].w = fast_ex2((v[k].w - m) * LOG2E);
            sum += (e[k].x + e[k].y) + (e[k].z + e[k].w);
        }
        #pragma unroll
        for (int o = 16; o; o >>= 1) sum += __shfl_xor_sync(0xffffffffu, sum, o);
        float inv = 1.0f / sum;

        #pragma unroll
        for (int k = 0; k < 4; k++) {
            float4 a = make_float4(e[k].x*inv, e[k].y*inv, e[k].z*inv, e[k].w*inv);
            *(float4*)(s + (k*32 + lane)*4) = a;
            int col = (k*32 + lane)*4;
            sm[r][col+0] = a.x; sm[r][col+1] = a.y; sm[r][col+2] = a.z; sm[r][col+3] = a.w;
        }
    }
    __syncthreads();

    const int i = lane & 15;
    const int jb = wid * 64 + (lane >> 4) * 32;
    float* dst = out_at + (size_t)(b * TV) * TQ + q0 + i;
    #pragma unroll
    for (int jj = 0; jj < 32; jj++) {
        int j = jb + jj;
        dst[(size_t)j * TQ] = sm[i][j];
    }
}

// ---------------------------------------------------------------------------
// K4: context[b] = alignment[b] @ value[b] + fused query concat.
// Tile 64q x 32n, 128 threads, grid 256 (~2 blocks/SM). Thread = 4q x 4n
// (8 wide accs): per warp-k only 2 LDS.128 for 8 fma2 (LDS:FMA = 1:4).
// ---------------------------------------------------------------------------
__global__ __launch_bounds__(128) void context_kernel(
    const float* __restrict__ value, const float* __restrict__ query,
    float* __restrict__ out)
{
    __shared__ float sAT[16][68];   // [k][qrow], pitch 68 (16B-aligned rows)
    __shared__ float sB[16][36];    // [k][n],    pitch 36
    const int tid = threadIdx.x;
    const int b  = blockIdx.z;
    const int mb = blockIdx.y * 64;
    const int nb = blockIdx.x * 32;
    const float* A = g_score + (size_t)b * TQ * TV;
    const float* V = value + (size_t)b * TV * D_;
    float* C = out + (size_t)b * TQ * (2 * D_);
    const int tq = tid >> 3;       // 0..15 -> q rows 4tq..4tq+3
    const int tn = tid & 7;        // 0..7  -> n cols 4tn..4tn+3

    // loaders: A = 64x16 = 256 f4 (2/thread), B = 16x32 = 128 f4 (1/thread)
    const int a0r = tid >> 2,          a0k = tid & 3;
    const int a1r = (128 + tid) >> 2,  a1k = tid & 3;
    const int brow = tid >> 3,         bcv = tid & 7;

    u64 acc[4][2] = {};            // [qrow][npair]; lanes = (n, n+1)
    float4 av0 = *(const float4*)(A + (mb + a0r) * TV + a0k * 4);
    float4 av1 = *(const float4*)(A + (mb + a1r) * TV + a1k * 4);
    float4 bv  = *(const float4*)(V + brow * D_ + nb + bcv * 4);

    for (int kt = 0; kt < TV; kt += 16) {
        __syncthreads();
        sAT[a0k*4+0][a0r] = av0.x; sAT[a0k*4+1][a0r] = av0.y;
        sAT[a0k*4+2][a0r] = av0.z; sAT[a0k*4+3][a0r] = av0.w;
        sAT[a1k*4+0][a1r] = av1.x; sAT[a1k*4+1][a1r] = av1.y;
        sAT[a1k*4+2][a1r] = av1.z; sAT[a1k*4+3][a1r] = av1.w;
        *(float4*)&sB[brow][bcv*4] = bv;
        __syncthreads();
        if (kt + 16 < TV) {
            av0 = *(const float4*)(A + (mb + a0r) * TV + kt + 16 + a0k * 4);
            av1 = *(const float4*)(A + (mb + a1r) * TV + kt + 16 + a1k * 4);
            bv  = *(const float4*)(V + (kt + 16 + brow) * D_ + nb + bcv * 4);
        }
        #pragma unroll
        for (int k = 0; k < 16; k++) {
            float4 a4 = *(const float4*)&sAT[k][tq*4];
            ulonglong2 bq = *(const ulonglong2*)&sB[k][tn*4];
            u64 A0 = bc2(a4.x), A1 = bc2(a4.y), A2 = bc2(a4.z), A3 = bc2(a4.w);
            acc[0][0] = fma2(A0, bq.x, acc[0][0]);
            acc[0][1] = fma2(A0, bq.y, acc[0][1]);
            acc[1][0] = fma2(A1, bq.x, acc[1][0]);
            acc[1][1] = fma2(A1, bq.y, acc[1][1]);
            acc[2][0] = fma2(A2, bq.x, acc[2][0]);
            acc[2][1] = fma2(A2, bq.y, acc[2][1]);
            acc[3][0] = fma2(A3, bq.x, acc[3][0]);
            acc[3][1] = fma2(A3, bq.y, acc[3][1]);
        }
    }
    #pragma unroll
    for (int i = 0; i < 4; i++) {
        float lo0, hi0, lo1, hi1;
        upk2(acc[i][0], lo0, hi0);
        upk2(acc[i][1], lo1, hi1);
        *(float4*)(C + (mb + tq*4 + i) * (2 * D_) + nb + tn*4) =
            make_float4(lo0, hi0, lo1, hi1);
    }

    // fused query concat: out[b][mb..][D + nb..] = query[b][mb..][nb..]
    const float* Q = query + (size_t)b * TQ * D_;
    #pragma unroll
    for (int i = 0; i < 4; i++) {
        int idx = i * 128 + tid;               // 512 float4s in 64x32 block
        int r = idx >> 3, c = idx & 7;
        *(float4*)(C + (mb + r) * (2 * D_) + D_ + nb + c*4) =
            *(const float4*)(Q + (mb + r) * D_ + nb + c*4);
    }
}

// ---------------------------------------------------------------------------
extern "C" void kernel_launch(void* const* d_in, const int* in_sizes, int n_in,
                              void* d_out, int out_size)
{
    const float* query = (const float*)d_in[0];   // [8,256,256]
    const float* value = (const float*)d_in[1];   // [8,512,256]
    const float* W1    = (const float*)d_in[2];   // [256,256]
    const float* b1    = (const float*)d_in[3];   // [256]
    const float* W2    = (const float*)d_in[4];   // [256,256]
    const float* b2    = (const float*)d_in[5];   // [256]
    float* out = (float*)d_out;

    void *qp_, *vp_;
    cudaGetSymbolAddress(&qp_, g_qproj);
    cudaGetSymbolAddress(&vp_, g_vproj);

    proj_kernel<<<dim3(4, 96), 256>>>(query, value, W1, b1, W2, b2,
                                      (float*)qp_, (float*)vp_);
    score_kernel<<<dim3(16, 4, 8), 256>>>();
    softmax_kernel<<<128, 256>>>(out + B_ * TQ * 2 * D_);
    context_kernel<<<dim3(8, 4, 8), 128>>>(value, query, out);
}